// round 6
// baseline (speedup 1.0000x reference)
#include <cuda_runtime.h>

// Problem constants (fixed for this checkpoint)
#define S 4096
#define I 1024
#define C 8
#define H 8
#define NSB 16            // k1 s-blocks
#define SB (S / NSB)      // 256
#define TI 16
#define NSPLIT 8          // k2 s-splits
#define SSPL (S / NSPLIT) // 512

// Scratch (static __device__ arrays per harness rules)
__device__ float2 g_kv[S * I];               // (k,v) per (s,i)  ~33.5 MB
__device__ float  g_qpart[NSB * I * 9];      // per-s-block {qsum[8], msum}
__device__ float2 g_part[I * H * NSPLIT];    // per-split (sum, ov) partials
__device__ float  g_o[I * H];                // attention output per (i,h)

// ---- f32x2 packed helpers (Blackwell FFMA2; only reachable via PTX) -------
typedef unsigned long long u64;
__device__ __forceinline__ u64 pk2(float lo, float hi) {
    u64 r; asm("mov.b64 %0, {%1,%2};" : "=l"(r) : "f"(lo), "f"(hi)); return r;
}
__device__ __forceinline__ float2 upk2(u64 v) {
    float2 f; asm("mov.b64 {%0,%1}, %2;" : "=f"(f.x), "=f"(f.y) : "l"(v)); return f;
}
#define FMA2(d, a, b, c) asm("fma.rn.f32x2 %0, %1, %2, %3;" : "=l"(d) : "l"(a), "l"(b), "l"(c))
#define ADD2(d, a, b)    asm("add.rn.f32x2 %0, %1, %2;" : "=l"(d) : "l"(a), "l"(b))
#define MUL2(d, a, b)    asm("mul.rn.f32x2 %0, %1, %2;" : "=l"(d) : "l"(a), "l"(b))

__device__ __forceinline__ float ex2f(float x) {
    float r; asm("ex2.approx.f32 %0, %1;" : "=f"(r) : "f"(x)); return r;
}
__device__ __forceinline__ float rcpf(float x) {
    float r; asm("rcp.approx.f32 %0, %1;" : "=f"(r) : "f"(x)); return r;
}
#define LOG2E 1.44269504f

// ---------------------------------------------------------------------------
// K1: per (s,i) layernorm -> (k,v) via one packed FMA2 chain + masked
//     mean-pool partial sums (restructured: A[c]=sum t*x[c], B1=sum t*mu).
// ---------------------------------------------------------------------------
__global__ __launch_bounds__(256) void k1(const float* __restrict__ m,
                                          const float* __restrict__ mask,
                                          const float* __restrict__ lnw,
                                          const float* __restrict__ lnb,
                                          const float* __restrict__ wk,
                                          const float* __restrict__ wv)
{
    const int il = threadIdx.x & (TI - 1);
    const int sl = threadIdx.x >> 4;          // 0..15
    const int i0 = blockIdx.x * TI;
    const int s0 = blockIdx.y * SB;
    const int i  = i0 + il;

    float LW[C], LB[C];
    u64 W2[C];                                 // (wk*lnw, wv*lnw) per c
    float WKs = 0.f, WVs = 0.f, WKb = 0.f, WVb = 0.f;
#pragma unroll
    for (int c = 0; c < C; ++c) {
        LW[c] = lnw[c]; LB[c] = lnb[c];
        const float wkf = wk[c] * LW[c], wvf = wv[c] * LW[c];
        W2[c] = pk2(wkf, wvf);
        WKs += wkf; WVs += wvf;
        WKb += wk[c] * LB[c]; WVb += wv[c] * LB[c];
    }
    const u64 WS2n = pk2(-WKs, -WVs);
    const u64 WB2  = pk2(WKb, WVb);

    u64 A2[4] = {0ull, 0ull, 0ull, 0ull};      // packed pooled sums
    float B1 = 0.f, Ms = 0.f;

    for (int jb = 0; jb < SB / 16 / 4; ++jb) {
        float4 a[4], b[4]; float mk[4]; int sArr[4];
#pragma unroll
        for (int u = 0; u < 4; ++u) {
            const int s = s0 + sl + (jb * 4 + u) * 16;
            sArr[u] = s;
            const float4* mp = (const float4*)(m + ((size_t)s * I + i) * C);
            a[u] = mp[0]; b[u] = mp[1];
            mk[u] = mask[(size_t)s * I + i];
        }
#pragma unroll
        for (int u = 0; u < 4; ++u) {
            u64 x2[4] = {pk2(a[u].x, a[u].y), pk2(a[u].z, a[u].w),
                         pk2(b[u].x, b[u].y), pk2(b[u].z, b[u].w)};
            // mean
            u64 s01, s23, ssum;
            ADD2(s01, x2[0], x2[1]); ADD2(s23, x2[2], x2[3]); ADD2(ssum, s01, s23);
            const float2 sf = upk2(ssum);
            const float mu = (sf.x + sf.y) * 0.125f;
            // E[x^2]
            u64 qq;
            MUL2(qq, x2[0], x2[0]);
            FMA2(qq, x2[1], x2[1], qq);
            FMA2(qq, x2[2], x2[2], qq);
            FMA2(qq, x2[3], x2[3], qq);
            const float2 qf = upk2(qq);
            const float var = (qf.x + qf.y) * 0.125f - mu * mu;
            const float rstd = rsqrtf(var + 1e-5f);

            // packed (k,v)
            const float xs[C] = {a[u].x, a[u].y, a[u].z, a[u].w,
                                 b[u].x, b[u].y, b[u].z, b[u].w};
            u64 d2 = 0ull;
#pragma unroll
            for (int c = 0; c < C; ++c) {
                const u64 xd = pk2(xs[c], xs[c]);
                FMA2(d2, xd, W2[c], d2);
            }
            const u64 mu2 = pk2(mu, mu), rstd2 = pk2(rstd, rstd);
            u64 t1; FMA2(t1, mu2, WS2n, d2);      // d - mu*Wsum
            u64 kv2; FMA2(kv2, rstd2, t1, WB2);
            const float2 kvf = upk2(kv2);
            g_kv[(size_t)sArr[u] * I + i] = make_float2(kvf.x, kvf.y);

            // pooled sums
            const float tt = mk[u] * rstd;
            const u64 t2 = pk2(tt, tt);
            FMA2(A2[0], t2, x2[0], A2[0]);
            FMA2(A2[1], t2, x2[1], A2[1]);
            FMA2(A2[2], t2, x2[2], A2[2]);
            FMA2(A2[3], t2, x2[3], A2[3]);
            B1 = fmaf(tt, mu, B1);
            Ms += mk[u];
        }
    }

    // finalize qs[c] = LW[c]*(A[c]-B1) + LB[c]*Ms
    float qs[C];
#pragma unroll
    for (int j = 0; j < 4; ++j) {
        const float2 av = upk2(A2[j]);
        qs[2 * j]     = LW[2 * j]     * (av.x - B1) + LB[2 * j]     * Ms;
        qs[2 * j + 1] = LW[2 * j + 1] * (av.y - B1) + LB[2 * j + 1] * Ms;
    }

    __shared__ float red[16][TI][9];
#pragma unroll
    for (int c = 0; c < C; ++c) red[sl][il][c] = qs[c];
    red[sl][il][8] = Ms;
    __syncthreads();

    const int t = threadIdx.x;
    if (t < TI * 9) {
        const int ril = t / 9, rc = t % 9;
        float sum = 0.f;
#pragma unroll
        for (int r = 0; r < 16; ++r) sum += red[r][ril][rc];
        g_qpart[((size_t)blockIdx.y * I + (i0 + ril)) * 9 + rc] = sum;
    }
}

// ---------------------------------------------------------------------------
// K2: single-pass (no max subtraction: logits are O(0.01); masked terms give
//     ex2(-1.4e9)=0 exactly). Grid (I/8, NSPLIT). Each thread: 16 s-values,
//     batched 4. One smem reduction round, stride-17 padded.
// ---------------------------------------------------------------------------
__global__ __launch_bounds__(256) void k2(const float* __restrict__ mask,
                                          const float* __restrict__ wq)
{
    const int t  = threadIdx.x;
    const int i0 = blockIdx.x * 8;
    const int sp = blockIdx.y;
    const int s0 = sp * SSPL;

    __shared__ float qp[8][9];
    __shared__ float shq[8][8];
    __shared__ float sred[256 * 17];

    if (t < 72) {
        const int il = t / 9, c = t % 9;
        float sum = 0.f;
#pragma unroll
        for (int nb = 0; nb < NSB; ++nb)
            sum += g_qpart[((size_t)nb * I + i0 + il) * 9 + c];
        qp[il][c] = sum;
    }
    __syncthreads();
    if (t < 64) {
        const int il = t >> 3, h = t & 7;
        const float inv = 1.0f / (qp[il][8] + 1e-5f);
        float q = 0.f;
#pragma unroll
        for (int c = 0; c < C; ++c) q += (qp[il][c] * inv) * wq[h * C + c];
        shq[il][h] = q;   // c_h^-0.5 = 1
    }
    __syncthreads();

    const int il = t & 7;
    const int sl = t >> 3;        // 0..31
    const int i  = i0 + il;

    float q[H];
#pragma unroll
    for (int h = 0; h < H; ++h) q[h] = shq[il][h];

    float sm[H], ov[H];
#pragma unroll
    for (int h = 0; h < H; ++h) { sm[h] = 0.f; ov[h] = 0.f; }

    for (int jb = 0; jb < 4; ++jb) {
        float2 kv[4]; float mk[4];
#pragma unroll
        for (int u = 0; u < 4; ++u) {
            const int s = s0 + sl + (jb * 4 + u) * 32;
            kv[u] = g_kv[(size_t)s * I + i];
            mk[u] = mask[(size_t)s * I + i];
        }
#pragma unroll
        for (int u = 0; u < 4; ++u) {
            const float b = 1e9f * (mk[u] - 1.0f);
#pragma unroll
            for (int h = 0; h < H; ++h) {
                const float l = fmaf(q[h], kv[u].x, b);
                const float p = ex2f(l * LOG2E);
                sm[h] += p;
                ov[h] = fmaf(p, kv[u].y, ov[h]);
            }
        }
    }

#pragma unroll
    for (int h = 0; h < H; ++h) {
        sred[t * 17 + h]     = sm[h];
        sred[t * 17 + 8 + h] = ov[h];
    }
    __syncthreads();
    if (t < 64) {
        const int ril = t >> 3, h = t & 7;
        float Ssum = 0.f, OV = 0.f;
#pragma unroll
        for (int r = 0; r < 32; ++r) {
            Ssum += sred[(ril + 8 * r) * 17 + h];
            OV   += sred[(ril + 8 * r) * 17 + 8 + h];
        }
        g_part[((size_t)(i0 + ril) * H + h) * NSPLIT + sp] = make_float2(Ssum, OV);
    }
}

// ---------------------------------------------------------------------------
// K2b: combine split partials -> g_o. One thread per (i,h).
// ---------------------------------------------------------------------------
__global__ __launch_bounds__(256) void k2b()
{
    const int id = blockIdx.x * 256 + threadIdx.x;   // 0..8191
    float Ssum = 0.f, OV = 0.f;
#pragma unroll
    for (int sp = 0; sp < NSPLIT; ++sp) {
        const float2 p = g_part[(size_t)id * NSPLIT + sp];
        Ssum += p.x; OV += p.y;
    }
    g_o[id] = OV / Ssum;
}

// ---------------------------------------------------------------------------
// K3: per (s,i): LN stats, gate, out = (o[i]*g)@wo^T + bo. Packed FFMA2,
//     O folded into WO, explicit double-buffered prefetch (batch 4),
//     raw ex2/rcp sigmoid. 1024 CTAs, i loop-invariant, 16 points/thread.
// ---------------------------------------------------------------------------
#define K3_BLOCKS 1024
#define K3_STRIDE (K3_BLOCKS * 256)   // 262144

__global__ __launch_bounds__(256) void k3(const float* __restrict__ m,
                                          const float* __restrict__ lnw,
                                          const float* __restrict__ lnb,
                                          const float* __restrict__ wg,
                                          const float* __restrict__ bg,
                                          const float* __restrict__ wo,
                                          const float* __restrict__ bo,
                                          float* __restrict__ out)
{
    const int t  = threadIdx.x;
    const int gt = blockIdx.x * 256 + t;
    const int i  = gt & (I - 1);

    float LWr[C], LBr[C];
#pragma unroll
    for (int c = 0; c < C; ++c) { LWr[c] = __ldg(lnw + c); LBr[c] = __ldg(lnb + c); }

    float WGf[H][C], WGs[H], BGf[H];
#pragma unroll
    for (int h = 0; h < H; ++h) {
        float rs = 0.f, bb = __ldg(bg + h);
#pragma unroll
        for (int c = 0; c < C; ++c) {
            const float w = __ldg(wg + h * C + c);
            WGf[h][c] = w * LWr[c];
            rs += WGf[h][c];
            bb += w * LBr[c];
        }
        WGs[h] = rs; BGf[h] = bb;
    }

    float O[H];
#pragma unroll
    for (int h = 0; h < H; ++h) O[h] = g_o[i * H + h];

    u64 WG2[4][C], WGs2[4], BGf2[4];
#pragma unroll
    for (int p = 0; p < 4; ++p) {
#pragma unroll
        for (int c = 0; c < C; ++c) WG2[p][c] = pk2(WGf[2 * p][c], WGf[2 * p + 1][c]);
        WGs2[p] = pk2(-WGs[2 * p], -WGs[2 * p + 1]);
        BGf2[p] = pk2(BGf[2 * p], BGf[2 * p + 1]);
    }
    u64 WO2[4][H], BO2[4];
#pragma unroll
    for (int qq = 0; qq < 4; ++qq) {
#pragma unroll
        for (int h = 0; h < H; ++h)
            WO2[qq][h] = pk2(O[h] * __ldg(wo + (2 * qq) * H + h),
                             O[h] * __ldg(wo + (2 * qq + 1) * H + h));
        BO2[qq] = pk2(__ldg(bo + 2 * qq), __ldg(bo + 2 * qq + 1));
    }

    float4 A4[2][4], B4[2][4];

    auto loadb = [&](int slot, int itv) {
#pragma unroll
        for (int u = 0; u < 4; ++u) {
            const float4* mp = (const float4*)(m + ((size_t)gt + (size_t)(itv * 4 + u) * K3_STRIDE) * C);
            A4[slot][u] = mp[0];
            B4[slot][u] = mp[1];
        }
    };

    loadb(0, 0);
    for (int it = 0; it < 4; ++it) {
        const int cur = it & 1;
        if (it < 3) loadb(cur ^ 1, it + 1);

#pragma unroll
        for (int u = 0; u < 4; ++u) {
            const float4 a = A4[cur][u], b = B4[cur][u];
            const float x[C] = {a.x, a.y, a.z, a.w, b.x, b.y, b.z, b.w};
            float mu = 0.f;
#pragma unroll
            for (int c = 0; c < C; ++c) mu += x[c];
            mu *= (1.0f / C);
            float var = 0.f;
#pragma unroll
            for (int c = 0; c < C; ++c) { const float d = x[c] - mu; var += d * d; }
            var *= (1.0f / C);
            const float rstd = rsqrtf(var + 1e-5f);
            const float murs = mu * rstd;

            u64 xd[C];
#pragma unroll
            for (int c = 0; c < C; ++c) xd[c] = pk2(x[c], x[c]);
            const u64 rstd2 = pk2(rstd, rstd);
            const u64 murs2 = pk2(murs, murs);

            u64 z2[4];
#pragma unroll
            for (int p = 0; p < 4; ++p) {
                u64 D = 0ull;
#pragma unroll
                for (int c = 0; c < C; ++c) FMA2(D, xd[c], WG2[p][c], D);
                u64 T; FMA2(T, murs2, WGs2[p], BGf2[p]);   // WGs2 pre-negated
                FMA2(z2[p], rstd2, D, T);
            }

            u64 gd2[H];
#pragma unroll
            for (int p = 0; p < 4; ++p) {
                const float2 z = upk2(z2[p]);
                const float s0v = rcpf(1.0f + ex2f(z.x * -LOG2E));
                const float s1v = rcpf(1.0f + ex2f(z.y * -LOG2E));
                gd2[2 * p]     = pk2(s0v, s0v);
                gd2[2 * p + 1] = pk2(s1v, s1v);
            }

            u64 acc2[4];
#pragma unroll
            for (int qq = 0; qq < 4; ++qq) {
                u64 A = BO2[qq];
#pragma unroll
                for (int h = 0; h < H; ++h) FMA2(A, gd2[h], WO2[qq][h], A);
                acc2[qq] = A;
            }

            const float2 r0 = upk2(acc2[0]), r1 = upk2(acc2[1]);
            const float2 r2 = upk2(acc2[2]), r3 = upk2(acc2[3]);
            float4* op = (float4*)(out + ((size_t)gt + (size_t)(it * 4 + u) * K3_STRIDE) * C);
            op[0] = make_float4(r0.x, r0.y, r1.x, r1.y);
            op[1] = make_float4(r2.x, r2.y, r3.x, r3.y);
        }
    }
}

// ---------------------------------------------------------------------------
extern "C" void kernel_launch(void* const* d_in, const int* in_sizes, int n_in,
                              void* d_out, int out_size)
{
    const float* m    = (const float*)d_in[0];
    const float* mask = (const float*)d_in[1];
    const float* lnw  = (const float*)d_in[2];
    const float* lnb  = (const float*)d_in[3];
    const float* wq   = (const float*)d_in[4];
    const float* wk   = (const float*)d_in[5];
    const float* wv   = (const float*)d_in[6];
    const float* wg   = (const float*)d_in[7];
    const float* bg   = (const float*)d_in[8];
    const float* wo   = (const float*)d_in[9];
    const float* bo   = (const float*)d_in[10];
    float* out = (float*)d_out;

    dim3 g1(I / TI, NSB);
    k1<<<g1, 256>>>(m, mask, lnw, lnb, wk, wv);
    dim3 g2(I / 8, NSPLIT);
    k2<<<g2, 256>>>(mask, wq);
    k2b<<<(I * H) / 256, 256>>>();
    k3<<<K3_BLOCKS, 256>>>(m, lnw, lnb, wg, bg, wo, bo, out);
}

// round 7
// speedup vs baseline: 1.4660x; 1.4660x over previous
#include <cuda_runtime.h>

// Problem constants (fixed for this checkpoint)
#define S 4096
#define I 1024
#define C 8
#define H 8
#define NSB 16            // k1 s-blocks
#define SB (S / NSB)      // 256
#define TI 16
#define NSPLIT 8          // k2 s-splits
#define SSPL (S / NSPLIT) // 512

// Scratch (static __device__ arrays per harness rules)
__device__ float2 g_kv[S * I];               // (k,v) per (s,i)  ~33.5 MB
__device__ float  g_qpart[NSB * I * 9];      // per-s-block {qsum[8], msum}
__device__ float2 g_part[I * H * NSPLIT];    // per-split (sum, ov) partials
__device__ float  g_o[I * H];                // attention output per (i,h)

// ---- f32x2 packed helpers (Blackwell FFMA2; only reachable via PTX) -------
typedef unsigned long long u64;
__device__ __forceinline__ u64 pk2(float lo, float hi) {
    u64 r; asm("mov.b64 %0, {%1,%2};" : "=l"(r) : "f"(lo), "f"(hi)); return r;
}
__device__ __forceinline__ float2 upk2(u64 v) {
    float2 f; asm("mov.b64 {%0,%1}, %2;" : "=f"(f.x), "=f"(f.y) : "l"(v)); return f;
}
#define FMA2(d, a, b, c) asm("fma.rn.f32x2 %0, %1, %2, %3;" : "=l"(d) : "l"(a), "l"(b), "l"(c))
#define ADD2(d, a, b)    asm("add.rn.f32x2 %0, %1, %2;" : "=l"(d) : "l"(a), "l"(b))
#define MUL2(d, a, b)    asm("mul.rn.f32x2 %0, %1, %2;" : "=l"(d) : "l"(a), "l"(b))

__device__ __forceinline__ float ex2f(float x) {
    float r; asm("ex2.approx.f32 %0, %1;" : "=f"(r) : "f"(x)); return r;
}
__device__ __forceinline__ float tanhfa(float x) {
    float r; asm("tanh.approx.f32 %0, %1;" : "=f"(r) : "f"(x)); return r;
}
#define LOG2E 1.44269504f

// ---------------------------------------------------------------------------
// K1: per (s,i) LN -> (k,v) + masked mean-pool partials. c-pair f32x2 packing,
//     LN folded into k/v weights, fully unrolled 4x batch-4.
// ---------------------------------------------------------------------------
__global__ __launch_bounds__(256, 2) void k1(const float* __restrict__ m,
                                             const float* __restrict__ mask,
                                             const float* __restrict__ lnw,
                                             const float* __restrict__ lnb,
                                             const float* __restrict__ wk,
                                             const float* __restrict__ wv)
{
    const int il = threadIdx.x & (TI - 1);
    const int sl = threadIdx.x >> 4;          // 0..15
    const int i0 = blockIdx.x * TI;
    const int s0 = blockIdx.y * SB;
    const int i  = i0 + il;

    // Folded: k = rstd*(dk - mu*WKs) + WKb, dk = sum_c (wk*lnw)[c]*x[c]
    u64 Wk2[4], Wv2[4];
    float WKs = 0.f, WVs = 0.f, WKb = 0.f, WVb = 0.f;
#pragma unroll
    for (int j = 0; j < 4; ++j) {
        const float k0 = __ldg(wk + 2 * j) * __ldg(lnw + 2 * j);
        const float k1v = __ldg(wk + 2 * j + 1) * __ldg(lnw + 2 * j + 1);
        const float v0 = __ldg(wv + 2 * j) * __ldg(lnw + 2 * j);
        const float v1 = __ldg(wv + 2 * j + 1) * __ldg(lnw + 2 * j + 1);
        Wk2[j] = pk2(k0, k1v); Wv2[j] = pk2(v0, v1);
        WKs += k0 + k1v; WVs += v0 + v1;
        WKb += __ldg(wk + 2 * j) * __ldg(lnb + 2 * j) + __ldg(wk + 2 * j + 1) * __ldg(lnb + 2 * j + 1);
        WVb += __ldg(wv + 2 * j) * __ldg(lnb + 2 * j) + __ldg(wv + 2 * j + 1) * __ldg(lnb + 2 * j + 1);
    }

    u64 A2[4] = {0ull, 0ull, 0ull, 0ull};      // packed pooled sums (c-pairs)
    float B1 = 0.f, Ms = 0.f;

#pragma unroll
    for (int jb = 0; jb < 4; ++jb) {
        float4 a[4], b[4]; float mk[4]; int sArr[4];
#pragma unroll
        for (int u = 0; u < 4; ++u) {
            const int s = s0 + sl + (jb * 4 + u) * 16;
            sArr[u] = s;
            const float4* mp = (const float4*)(m + ((size_t)s * I + i) * C);
            a[u] = mp[0]; b[u] = mp[1];
            mk[u] = mask[(size_t)s * I + i];
        }
#pragma unroll
        for (int u = 0; u < 4; ++u) {
            u64 x2[4] = {pk2(a[u].x, a[u].y), pk2(a[u].z, a[u].w),
                         pk2(b[u].x, b[u].y), pk2(b[u].z, b[u].w)};
            // mean
            u64 s01, s23, ssum;
            ADD2(s01, x2[0], x2[1]); ADD2(s23, x2[2], x2[3]); ADD2(ssum, s01, s23);
            const float2 sf = upk2(ssum);
            const float mu = (sf.x + sf.y) * 0.125f;
            // var = E[x^2] - mu^2
            u64 qq;
            MUL2(qq, x2[0], x2[0]);
            FMA2(qq, x2[1], x2[1], qq);
            FMA2(qq, x2[2], x2[2], qq);
            FMA2(qq, x2[3], x2[3], qq);
            const float2 qf = upk2(qq);
            const float var = fmaf(-mu, mu, (qf.x + qf.y) * 0.125f);
            const float rstd = rsqrtf(var + 1e-5f);

            // dk, dv via c-pair dot products
            u64 dk2, dv2;
            MUL2(dk2, x2[0], Wk2[0]);
            FMA2(dk2, x2[1], Wk2[1], dk2);
            FMA2(dk2, x2[2], Wk2[2], dk2);
            FMA2(dk2, x2[3], Wk2[3], dk2);
            MUL2(dv2, x2[0], Wv2[0]);
            FMA2(dv2, x2[1], Wv2[1], dv2);
            FMA2(dv2, x2[2], Wv2[2], dv2);
            FMA2(dv2, x2[3], Wv2[3], dv2);
            const float2 dkf = upk2(dk2), dvf = upk2(dv2);
            const float kk = fmaf(rstd, fmaf(-mu, WKs, dkf.x + dkf.y), WKb);
            const float vv = fmaf(rstd, fmaf(-mu, WVs, dvf.x + dvf.y), WVb);
            g_kv[(size_t)sArr[u] * I + i] = make_float2(kk, vv);

            // pooled sums
            const float tt = mk[u] * rstd;
            const u64 t2 = pk2(tt, tt);
            FMA2(A2[0], t2, x2[0], A2[0]);
            FMA2(A2[1], t2, x2[1], A2[1]);
            FMA2(A2[2], t2, x2[2], A2[2]);
            FMA2(A2[3], t2, x2[3], A2[3]);
            B1 = fmaf(tt, mu, B1);
            Ms += mk[u];
        }
    }

    // finalize qs[c] = LW[c]*(A[c]-B1) + LB[c]*Ms   (LW/LB loaded post-loop)
    float qs[C];
#pragma unroll
    for (int j = 0; j < 4; ++j) {
        const float2 av = upk2(A2[j]);
        qs[2 * j]     = __ldg(lnw + 2 * j)     * (av.x - B1) + __ldg(lnb + 2 * j)     * Ms;
        qs[2 * j + 1] = __ldg(lnw + 2 * j + 1) * (av.y - B1) + __ldg(lnb + 2 * j + 1) * Ms;
    }

    __shared__ float red[16][TI][9];
#pragma unroll
    for (int c = 0; c < C; ++c) red[sl][il][c] = qs[c];
    red[sl][il][8] = Ms;
    __syncthreads();

    const int t = threadIdx.x;
    if (t < TI * 9) {
        const int ril = t / 9, rc = t % 9;
        float sum = 0.f;
#pragma unroll
        for (int r = 0; r < 16; ++r) sum += red[r][ril][rc];
        g_qpart[((size_t)blockIdx.y * I + (i0 + ril)) * 9 + rc] = sum;
    }
}

// ---------------------------------------------------------------------------
// K2: single-pass softmax (no max subtraction: logits are O(0.01); masked
//     terms give ex2(-1.4e9)=0 exactly). Grid (I/8, NSPLIT).
// ---------------------------------------------------------------------------
__global__ __launch_bounds__(256, 2) void k2(const float* __restrict__ mask,
                                             const float* __restrict__ wq)
{
    const int t  = threadIdx.x;
    const int i0 = blockIdx.x * 8;
    const int sp = blockIdx.y;
    const int s0 = sp * SSPL;

    __shared__ float qp[8][9];
    __shared__ float shq[8][8];
    __shared__ float sred[256 * 17];

    if (t < 72) {
        const int il = t / 9, c = t % 9;
        float sum = 0.f;
#pragma unroll
        for (int nb = 0; nb < NSB; ++nb)
            sum += g_qpart[((size_t)nb * I + i0 + il) * 9 + c];
        qp[il][c] = sum;
    }
    __syncthreads();
    if (t < 64) {
        const int il = t >> 3, h = t & 7;
        const float inv = 1.0f / (qp[il][8] + 1e-5f);
        float q = 0.f;
#pragma unroll
        for (int c = 0; c < C; ++c) q += (qp[il][c] * inv) * wq[h * C + c];
        shq[il][h] = q;   // c_h^-0.5 = 1
    }
    __syncthreads();

    const int il = t & 7;
    const int sl = t >> 3;        // 0..31
    const int i  = i0 + il;

    float q[H];
#pragma unroll
    for (int h = 0; h < H; ++h) q[h] = shq[il][h];

    float sm[H], ov[H];
#pragma unroll
    for (int h = 0; h < H; ++h) { sm[h] = 0.f; ov[h] = 0.f; }

#pragma unroll
    for (int jb = 0; jb < 4; ++jb) {
        float2 kv[4]; float mk[4];
#pragma unroll
        for (int u = 0; u < 4; ++u) {
            const int s = s0 + sl + (jb * 4 + u) * 32;
            kv[u] = g_kv[(size_t)s * I + i];
            mk[u] = mask[(size_t)s * I + i];
        }
#pragma unroll
        for (int u = 0; u < 4; ++u) {
            const float b = 1e9f * (mk[u] - 1.0f);
#pragma unroll
            for (int h = 0; h < H; ++h) {
                const float l = fmaf(q[h], kv[u].x, b);
                const float p = ex2f(l * LOG2E);
                sm[h] += p;
                ov[h] = fmaf(p, kv[u].y, ov[h]);
            }
        }
    }

#pragma unroll
    for (int h = 0; h < H; ++h) {
        sred[t * 17 + h]     = sm[h];
        sred[t * 17 + 8 + h] = ov[h];
    }
    __syncthreads();
    if (t < 64) {
        const int ril = t >> 3, h = t & 7;
        float Ssum = 0.f, OV = 0.f;
#pragma unroll
        for (int r = 0; r < 32; ++r) {
            Ssum += sred[(ril + 8 * r) * 17 + h];
            OV   += sred[(ril + 8 * r) * 17 + 8 + h];
        }
        g_part[((size_t)(i0 + ril) * H + h) * NSPLIT + sp] = make_float2(Ssum, OV);
    }
}

// ---------------------------------------------------------------------------
// K2b: combine split partials -> g_o. One thread per (i,h).
// ---------------------------------------------------------------------------
__global__ __launch_bounds__(256) void k2b()
{
    const int id = blockIdx.x * 256 + threadIdx.x;   // 0..8191
    float Ssum = 0.f, OV = 0.f;
#pragma unroll
    for (int sp = 0; sp < NSPLIT; ++sp) {
        const float2 p = g_part[(size_t)id * NSPLIT + sp];
        Ssum += p.x; OV += p.y;
    }
    g_o[id] = OV / Ssum;
}

// ---------------------------------------------------------------------------
// K3: per (s,i): LN, gate via tanh (sigma(z)=0.5(1+tanh(z/2)), 0.5 folded
//     into gate weights), out = (o*g)@wo^T + bo. Weights in SMEM (ptxas
//     hoists under the 128-reg cap). 128-thread CTAs, >=4 CTAs/SM.
//     2048 CTAs, i loop-invariant, 16 points/thread (4 x batch-4).
// ---------------------------------------------------------------------------
#define K3_BLOCKS 2048
#define K3_THREADS 128
#define K3_STRIDE (K3_BLOCKS * K3_THREADS)   // 262144

__global__ __launch_bounds__(K3_THREADS, 4) void k3(const float* __restrict__ m,
                                                    const float* __restrict__ lnw,
                                                    const float* __restrict__ lnb,
                                                    const float* __restrict__ wg,
                                                    const float* __restrict__ bg,
                                                    const float* __restrict__ wo,
                                                    const float* __restrict__ bo,
                                                    float* __restrict__ out)
{
    __shared__ u64   sWG2[H][4];   // (0.5*wg*lnw) c-pairs
    __shared__ float sBG[H];       // 0.5*(bg + wg@lnb)
    __shared__ u64   sWO2[H][4];   // wo c-pairs, per head
    __shared__ u64   sBO2[4];      // bo c-pairs

    const int t = threadIdx.x;
    if (t < 32) {
        const int h = t >> 2, j = t & 3;
        const float w0 = 0.5f * wg[h * C + 2 * j]     * lnw[2 * j];
        const float w1 = 0.5f * wg[h * C + 2 * j + 1] * lnw[2 * j + 1];
        sWG2[h][j] = pk2(w0, w1);
        sWO2[h][j] = pk2(wo[(2 * j) * H + h], wo[(2 * j + 1) * H + h]);
    }
    if (t >= 32 && t < 40) {
        const int h = t - 32;
        float bb = bg[h];
#pragma unroll
        for (int c = 0; c < C; ++c) bb += wg[h * C + c] * lnb[c];
        sBG[h] = 0.5f * bb;
    }
    if (t >= 40 && t < 44) {
        const int j = t - 40;
        sBO2[j] = pk2(bo[2 * j], bo[2 * j + 1]);
    }
    __syncthreads();

    const int gt = blockIdx.x * K3_THREADS + t;
    const int i  = gt & (I - 1);

    float O2[H];
#pragma unroll
    for (int h = 0; h < H; ++h) O2[h] = 0.5f * g_o[i * H + h];

#pragma unroll
    for (int it = 0; it < 4; ++it) {
        float4 a[4], b[4];
#pragma unroll
        for (int u = 0; u < 4; ++u) {
            const float4* mp = (const float4*)(m + ((size_t)gt + (size_t)(it * 4 + u) * K3_STRIDE) * C);
            a[u] = mp[0]; b[u] = mp[1];
        }
#pragma unroll
        for (int u = 0; u < 4; ++u) {
            u64 x2[4] = {pk2(a[u].x, a[u].y), pk2(a[u].z, a[u].w),
                         pk2(b[u].x, b[u].y), pk2(b[u].z, b[u].w)};
            u64 s01, s23, ssum;
            ADD2(s01, x2[0], x2[1]); ADD2(s23, x2[2], x2[3]); ADD2(ssum, s01, s23);
            const float2 sf = upk2(ssum);
            const float mu = (sf.x + sf.y) * 0.125f;
            u64 qq;
            MUL2(qq, x2[0], x2[0]);
            FMA2(qq, x2[1], x2[1], qq);
            FMA2(qq, x2[2], x2[2], qq);
            FMA2(qq, x2[3], x2[3], qq);
            const float2 qf = upk2(qq);
            const float var = fmaf(-mu, mu, (qf.x + qf.y) * 0.125f);
            const float rstd = rsqrtf(var + 1e-5f);
            const float nmurs = -mu * rstd;

            const u64 r2  = pk2(rstd, rstd);
            const u64 nm2 = pk2(nmurs, nmurs);
            u64 y2[4];
            FMA2(y2[0], x2[0], r2, nm2);
            FMA2(y2[1], x2[1], r2, nm2);
            FMA2(y2[2], x2[2], r2, nm2);
            FMA2(y2[3], x2[3], r2, nm2);

            float th[H];
#pragma unroll
            for (int h = 0; h < H; ++h) {
                u64 p;
                MUL2(p, y2[0], sWG2[h][0]);
                FMA2(p, y2[1], sWG2[h][1], p);
                FMA2(p, y2[2], sWG2[h][2], p);
                FMA2(p, y2[3], sWG2[h][3], p);
                const float2 pf = upk2(p);
                const float z = pf.x + pf.y + sBG[h];
                const float tv = tanhfa(z);
                th[h] = fmaf(O2[h], tv, O2[h]);
            }

            u64 acc[4] = {sBO2[0], sBO2[1], sBO2[2], sBO2[3]};
#pragma unroll
            for (int h = 0; h < H; ++h) {
                const u64 t2 = pk2(th[h], th[h]);
                FMA2(acc[0], t2, sWO2[h][0], acc[0]);
                FMA2(acc[1], t2, sWO2[h][1], acc[1]);
                FMA2(acc[2], t2, sWO2[h][2], acc[2]);
                FMA2(acc[3], t2, sWO2[h][3], acc[3]);
            }

            const float2 r0 = upk2(acc[0]), r1 = upk2(acc[1]);
            const float2 r2o = upk2(acc[2]), r3 = upk2(acc[3]);
            float4* op = (float4*)(out + ((size_t)gt + (size_t)(it * 4 + u) * K3_STRIDE) * C);
            op[0] = make_float4(r0.x, r0.y, r1.x, r1.y);
            op[1] = make_float4(r2o.x, r2o.y, r3.x, r3.y);
        }
    }
}

// ---------------------------------------------------------------------------
extern "C" void kernel_launch(void* const* d_in, const int* in_sizes, int n_in,
                              void* d_out, int out_size)
{
    const float* m    = (const float*)d_in[0];
    const float* mask = (const float*)d_in[1];
    const float* lnw  = (const float*)d_in[2];
    const float* lnb  = (const float*)d_in[3];
    const float* wq   = (const float*)d_in[4];
    const float* wk   = (const float*)d_in[5];
    const float* wv   = (const float*)d_in[6];
    const float* wg   = (const float*)d_in[7];
    const float* bg   = (const float*)d_in[8];
    const float* wo   = (const float*)d_in[9];
    const float* bo   = (const float*)d_in[10];
    float* out = (float*)d_out;

    dim3 g1(I / TI, NSB);
    k1<<<g1, 256>>>(m, mask, lnw, lnb, wk, wv);
    dim3 g2(I / 8, NSPLIT);
    k2<<<g2, 256>>>(mask, wq);
    k2b<<<(I * H) / 256, 256>>>();
    k3<<<K3_BLOCKS, K3_THREADS>>>(m, lnw, lnb, wg, bg, wo, bo, out);
}